// round 1
// baseline (speedup 1.0000x reference)
#include <cuda_runtime.h>
#include <math.h>

#define NN     1195
#define NUSER  805
#define NITEM  390
#define DD     64
#define BB     2048
#define KPAD   1280           // A col stride (20 tiles of 64)
#define RPAD   1216           // A row count padded (38 tiles of 32)
#define MATSZ  (RPAD*KPAD)

// ---------------- scratch (static device globals; no allocation) -------------
__device__ float d_A[3*MATSZ];        // dense adjacency counts, padded w/ zeros
__device__ float d_invcnt[3*RPAD];
__device__ float d_h1[NN*DD];
__device__ float d_y1[3*NN*DD];
__device__ float d_h2[3*NN*DD];
__device__ float d_y2[3*NN*DD];
__device__ float d_cu[NITEM*DD];
__device__ float d_ci[NUSER*DD];
__device__ float d_invcol[4*DD];
__device__ float d_es[BB*DD];
__device__ float d_hb[BB*DD];
__device__ float d_hn[BB*DD];
__device__ float d_mu[DD];
__device__ float d_istd[DD];

__device__ __forceinline__ float* buf(int id){
    switch(id){
        case 0: return d_h1;
        case 1: return d_y1;
        case 2: return d_h2;
        case 3: return d_y2;
        case 4: return d_es;
        case 5: return d_hb;
    }
    return d_hn;
}

// ---------------- zero adjacency ---------------------------------------------
__global__ void k_zeroA(){
    int i = blockIdx.x*blockDim.x + threadIdx.x;
    int n = 3*MATSZ/4;
    if (i < n) reinterpret_cast<float4*>(d_A)[i] = make_float4(0.f,0.f,0.f,0.f);
}

// ---------------- build adjacency counts -------------------------------------
__global__ void k_build(const int* __restrict__ e, int E, int g){
    int i = blockIdx.x*blockDim.x + threadIdx.x;
    if (i < E){
        int s = e[i];
        int d = e[E + i];
        atomicAdd(&d_A[(size_t)g*MATSZ + (size_t)d*KPAD + s], 1.0f);
    }
}

// ---------------- per-row 1/max(cnt,1) ---------------------------------------
__global__ void k_cnt(){
    int g    = blockIdx.y;
    int w    = threadIdx.x >> 5;
    int lane = threadIdx.x & 31;
    int row  = blockIdx.x*8 + w;
    if (row >= RPAD) return;
    const float* Ar = d_A + (size_t)g*MATSZ + (size_t)row*KPAD;
    float s = 0.f;
    #pragma unroll 8
    for (int k = lane; k < KPAD; k += 32) s += Ar[k];
    #pragma unroll
    for (int off = 16; off; off >>= 1) s += __shfl_xor_sync(0xffffffffu, s, off);
    if (!lane) d_invcnt[g*RPAD + row] = 1.f / fmaxf(s, 1.f);
}

// ---------------- out = x @ W^T + b  (D=64) ----------------------------------
__global__ void k_lin(const float* __restrict__ xext, int xid,
                      const float* __restrict__ W, const float* __restrict__ bias,
                      int outid, int nrows){
    const float* x = xext ? xext : buf(xid);
    float* o = buf(outid);
    __shared__ float Ws[64*65];
    int tx = threadIdx.x, ty = threadIdx.y;
    int tid = ty*64 + tx;
    for (int i = tid; i < 4096; i += 256){
        int r = i >> 6, c = i & 63;
        Ws[r*65 + c] = W[i];
    }
    __syncthreads();
    int n = blockIdx.x*4 + ty;
    if (n >= nrows) return;
    float acc = bias[tx];
    const float* xr = x + (size_t)n*64;
    #pragma unroll
    for (int k = 0; k < 64; k++) acc = fmaf(xr[k], Ws[tx*65 + k], acc);
    o[(size_t)n*64 + tx] = acc;
}

// ---------------- y = tanh(invcnt * (A @ h)) over 3 graphs -------------------
__global__ void k_agg(int hid, int gstride, int outid){
    int g = blockIdx.y;
    const float* A = d_A + (size_t)g*MATSZ;
    const float* h = buf(hid) + (size_t)g*gstride;
    float*       o = buf(outid) + (size_t)g*NN*DD;
    int tx = threadIdx.x;   // 0..15 : float4 column group
    int ty = threadIdx.y;   // 0..7  : 4-row group
    int tid = ty*16 + tx;
    __shared__ float4 hs[64*16];      // h tile: [64 k][16 float4]
    float4 a0 = make_float4(0,0,0,0), a1 = a0, a2 = a0, a3 = a0;
    int n0 = blockIdx.x*32;
    const float* Ar = A + (size_t)(n0 + ty*4)*KPAD;
    for (int k0 = 0; k0 < KPAD; k0 += 64){
        for (int i = tid; i < 1024; i += 128){
            int r = i >> 4, c = i & 15;
            int gk = k0 + r;
            hs[i] = (gk < NN) ? reinterpret_cast<const float4*>(h)[gk*16 + c]
                              : make_float4(0,0,0,0);
        }
        __syncthreads();
        #pragma unroll 4
        for (int j = 0; j < 64; j++){
            float4 hv = hs[j*16 + tx];
            float w0 = Ar[         k0 + j];
            float w1 = Ar[  KPAD + k0 + j];
            float w2 = Ar[2*KPAD + k0 + j];
            float w3 = Ar[3*KPAD + k0 + j];
            a0.x = fmaf(w0, hv.x, a0.x); a0.y = fmaf(w0, hv.y, a0.y);
            a0.z = fmaf(w0, hv.z, a0.z); a0.w = fmaf(w0, hv.w, a0.w);
            a1.x = fmaf(w1, hv.x, a1.x); a1.y = fmaf(w1, hv.y, a1.y);
            a1.z = fmaf(w1, hv.z, a1.z); a1.w = fmaf(w1, hv.w, a1.w);
            a2.x = fmaf(w2, hv.x, a2.x); a2.y = fmaf(w2, hv.y, a2.y);
            a2.z = fmaf(w2, hv.z, a2.z); a2.w = fmaf(w2, hv.w, a2.w);
            a3.x = fmaf(w3, hv.x, a3.x); a3.y = fmaf(w3, hv.y, a3.y);
            a3.z = fmaf(w3, hv.z, a3.z); a3.w = fmaf(w3, hv.w, a3.w);
        }
        __syncthreads();
    }
    float4 av[4] = {a0, a1, a2, a3};
    #pragma unroll
    for (int r = 0; r < 4; r++){
        int n = n0 + ty*4 + r;
        if (n < NN){
            float ic = d_invcnt[g*RPAD + n];
            float4 v;
            v.x = tanhf(ic*av[r].x); v.y = tanhf(ic*av[r].y);
            v.z = tanhf(ic*av[r].z); v.w = tanhf(ic*av[r].w);
            reinterpret_cast<float4*>(o)[n*16 + tx] = v;
        }
    }
}

// ---------------- column L2 inv-norms over user rows (4 matrices) ------------
__global__ void k_colnorm(const float* __restrict__ emb){
    int dcol = blockIdx.x, m = blockIdx.y;
    const float* x = (m == 0) ? emb
                   : (m == 1) ? d_y2 + NN*DD      // SH_g3  (sub_g1)
                   : (m == 2) ? d_y2              // x_SH6  (total_g)
                   :            d_y2 + 2*NN*DD;   // SH_g33 (sub_g2)
    float s = 0.f;
    for (int r = threadIdx.x; r < NUSER; r += 256){
        float v = x[(size_t)r*64 + dcol];
        s = fmaf(v, v, s);
    }
    __shared__ float sh[256];
    sh[threadIdx.x] = s; __syncthreads();
    for (int o = 128; o; o >>= 1){
        if (threadIdx.x < o) sh[threadIdx.x] += sh[threadIdx.x + o];
        __syncthreads();
    }
    if (!threadIdx.x) d_invcol[m*64 + dcol] = rsqrtf(sh[0]);
}

// ---------------- c_u : fused row-normalized item views ----------------------
__global__ void k_cu(const float* __restrict__ emb){
    int w    = threadIdx.x >> 5;
    int lane = threadIdx.x & 31;
    int r = blockIdx.x*8 + w;
    if (r >= NITEM) return;
    size_t row = (size_t)(NUSER + r)*64;
    const float* mats[4] = { emb, d_y2 + NN*DD, d_y2, d_y2 + 2*NN*DD };
    float o0 = 0.f, o1 = 0.f;
    #pragma unroll
    for (int m = 0; m < 4; m++){
        float a = mats[m][row + lane];
        float b = mats[m][row + lane + 32];
        float ss = a*a + b*b;
        #pragma unroll
        for (int off = 16; off; off >>= 1) ss += __shfl_xor_sync(0xffffffffu, ss, off);
        float inv = rsqrtf(ss);
        o0 = fmaf(a, inv, o0);
        o1 = fmaf(b, inv, o1);
    }
    d_cu[r*64 + lane]      = 0.25f*o0;
    d_cu[r*64 + lane + 32] = 0.25f*o1;
}

// ---------------- c_i : fused column-normalized user views -------------------
__global__ void k_ci(const float* __restrict__ emb){
    int i = blockIdx.x*256 + threadIdx.x;
    if (i >= NUSER*64) return;
    int dcol = i & 63;
    float v = emb[i]             * d_invcol[       dcol]
            + d_y2[NN*DD + i]    * d_invcol[ 64  + dcol]
            + d_y2[i]            * d_invcol[128  + dcol]
            + d_y2[2*NN*DD + i]  * d_invcol[192  + dcol];
    d_ci[i] = 0.25f*v;
}

// ---------------- e_synd = (presc @ c_u) / rowsum(presc) ---------------------
__global__ void k_esynd(const float* __restrict__ presc){
    int tx = threadIdx.x, ty = threadIdx.y;
    int tid = ty*16 + tx;
    int n = blockIdx.x*16 + ty;
    __shared__ float4 cus[64*16];
    float4 acc = make_float4(0,0,0,0);
    float rs = 0.f;
    for (int k0 = 0; k0 < NITEM; k0 += 64){
        for (int i = tid; i < 1024; i += 256){
            int r = i >> 4, c = i & 15;
            int gk = k0 + r;
            cus[i] = (gk < NITEM) ? reinterpret_cast<const float4*>(d_cu)[gk*16 + c]
                                  : make_float4(0,0,0,0);
        }
        __syncthreads();
        int jm = min(64, NITEM - k0);
        for (int j = 0; j < jm; j++){
            float a = presc[(size_t)n*NITEM + k0 + j];
            rs += a;
            float4 cv = cus[j*16 + tx];
            acc.x = fmaf(a, cv.x, acc.x); acc.y = fmaf(a, cv.y, acc.y);
            acc.z = fmaf(a, cv.z, acc.z); acc.w = fmaf(a, cv.w, acc.w);
        }
        __syncthreads();
    }
    float inv = 1.f/rs;
    float4 v = make_float4(acc.x*inv, acc.y*inv, acc.z*inv, acc.w*inv);
    reinterpret_cast<float4*>(d_es)[n*16 + tx] = v;
}

// ---------------- BN stats over batch ----------------------------------------
__global__ void k_bnstats(){
    int c = blockIdx.x;
    float s = 0.f, s2 = 0.f;
    for (int r = threadIdx.x; r < BB; r += 256){
        float v = d_hb[(size_t)r*64 + c];
        s += v; s2 = fmaf(v, v, s2);
    }
    __shared__ float sha[256], shb[256];
    sha[threadIdx.x] = s; shb[threadIdx.x] = s2; __syncthreads();
    for (int o = 128; o; o >>= 1){
        if (threadIdx.x < o){
            sha[threadIdx.x] += sha[threadIdx.x + o];
            shb[threadIdx.x] += shb[threadIdx.x + o];
        }
        __syncthreads();
    }
    if (!threadIdx.x){
        float mu  = sha[0] / (float)BB;
        float var = shb[0] / (float)BB - mu*mu;
        d_mu[c]   = mu;
        d_istd[c] = rsqrtf(var + 1e-5f);
    }
}

// ---------------- BN normalize + relu ----------------------------------------
__global__ void k_bnrelu(const float* __restrict__ gamma, const float* __restrict__ beta){
    int i = blockIdx.x*256 + threadIdx.x;
    if (i >= BB*64) return;
    int c = i & 63;
    float v = (d_hb[i] - d_mu[c]) * d_istd[c] * gamma[c] + beta[c];
    d_hn[i] = fmaxf(v, 0.f);
}

// ---------------- pre = hn @ c_i^T -------------------------------------------
__global__ void k_final(float* __restrict__ out){
    int tx = threadIdx.x, ty = threadIdx.y;
    int tid = ty*16 + tx;
    int j0 = blockIdx.x*64;
    int n0 = blockIdx.y*64;
    __shared__ float cit[64*68];   // cit[k][j], padded
    __shared__ float hsm[64*68];   // hsm[n][k], padded
    for (int i = tid; i < 1024; i += 256){
        int r = i >> 4, c4 = i & 15;
        *reinterpret_cast<float4*>(&hsm[r*68 + c4*4]) =
            reinterpret_cast<const float4*>(d_hn)[(size_t)(n0 + r)*16 + c4];
        float4 v = (j0 + r < NUSER)
            ? reinterpret_cast<const float4*>(d_ci)[(size_t)(j0 + r)*16 + c4]
            : make_float4(0,0,0,0);
        cit[(c4*4 + 0)*68 + r] = v.x;
        cit[(c4*4 + 1)*68 + r] = v.y;
        cit[(c4*4 + 2)*68 + r] = v.z;
        cit[(c4*4 + 3)*68 + r] = v.w;
    }
    __syncthreads();
    float4 acc[4] = { make_float4(0,0,0,0), make_float4(0,0,0,0),
                      make_float4(0,0,0,0), make_float4(0,0,0,0) };
    #pragma unroll 4
    for (int k = 0; k < 64; k++){
        float4 cj = *reinterpret_cast<const float4*>(&cit[k*68 + tx*4]);
        #pragma unroll
        for (int r = 0; r < 4; r++){
            float a = hsm[(ty*4 + r)*68 + k];
            acc[r].x = fmaf(a, cj.x, acc[r].x);
            acc[r].y = fmaf(a, cj.y, acc[r].y);
            acc[r].z = fmaf(a, cj.z, acc[r].z);
            acc[r].w = fmaf(a, cj.w, acc[r].w);
        }
    }
    #pragma unroll
    for (int r = 0; r < 4; r++){
        int n = n0 + ty*4 + r;
        int j = j0 + tx*4;
        float vals[4] = { acc[r].x, acc[r].y, acc[r].z, acc[r].w };
        #pragma unroll
        for (int c = 0; c < 4; c++)
            if (j + c < NUSER) out[(size_t)n*NUSER + j + c] = vals[c];
    }
}

// ---------------- launch -----------------------------------------------------
extern "C" void kernel_launch(void* const* d_in, const int* in_sizes, int n_in,
                              void* d_out, int out_size){
    const float* presc = (const float*)d_in[1];
    const float* emb   = (const float*)d_in[2];
    const float* W1    = (const float*)d_in[3];
    const float* b1    = (const float*)d_in[4];
    const float* W2    = (const float*)d_in[5];
    const float* b2    = (const float*)d_in[6];
    const float* mlpW  = (const float*)d_in[7];
    const float* mlpb  = (const float*)d_in[8];
    const float* gamma = (const float*)d_in[9];
    const float* beta  = (const float*)d_in[10];
    const int*   tg    = (const int*)d_in[11];
    const int*   sg1   = (const int*)d_in[12];
    const int*   sg2   = (const int*)d_in[13];
    int Et = in_sizes[11]/2;
    int E1 = in_sizes[12]/2;
    int E2 = in_sizes[13]/2;
    float* out = (float*)d_out;

    // adjacency build
    k_zeroA<<<(3*MATSZ/4 + 255)/256, 256>>>();
    k_build<<<(Et + 255)/256, 256>>>(tg,  Et, 0);
    k_build<<<(E1 + 255)/256, 256>>>(sg1, E1, 1);
    k_build<<<(E2 + 255)/256, 256>>>(sg2, E2, 2);
    k_cnt<<<dim3(RPAD/8, 3), 256>>>();

    // GCN layer 1 (shared linear transform) + layer 2
    k_lin<<<(NN + 3)/4, dim3(64,4)>>>(emb, -1, W1, b1, 0, NN);
    k_agg<<<dim3((NN + 31)/32, 3), dim3(16,8)>>>(0, 0, 1);
    k_lin<<<(3*NN + 3)/4, dim3(64,4)>>>(nullptr, 1, W2, b2, 2, 3*NN);
    k_agg<<<dim3((NN + 31)/32, 3), dim3(16,8)>>>(2, NN*DD, 3);

    // contrastive-view fusion
    k_colnorm<<<dim3(64,4), 256>>>(emb);
    k_cu<<<(NITEM + 7)/8, 256>>>(emb);
    k_ci<<<(NUSER*64 + 255)/256, 256>>>(emb);

    // prescription pooling -> MLP -> BN -> relu -> scores
    k_esynd<<<BB/16, dim3(16,16)>>>(presc);
    k_lin<<<BB/4, dim3(64,4)>>>(nullptr, 4, mlpW, mlpb, 5, BB);
    k_bnstats<<<64, 256>>>();
    k_bnrelu<<<(BB*64)/256, 256>>>(gamma, beta);
    k_final<<<dim3((NUSER + 63)/64, BB/64), dim3(16,16)>>>(out);
}

// round 2
// speedup vs baseline: 1.0904x; 1.0904x over previous
#include <cuda_runtime.h>
#include <math.h>

#define NN     1195
#define NUSER  805
#define NITEM  390
#define DD     64
#define BB     2048
#define KPAD   1216           // A col stride (19 tiles of 64, >= 1195)
#define RPAD   1216           // A row count padded (38 tiles of 32)
#define MATSZ  (RPAD*KPAD)

// ---------------- packed f32x2 helpers (Blackwell FFMA2) ---------------------
__device__ __forceinline__ void fma2(unsigned long long& d,
                                     unsigned long long a, unsigned long long b){
    asm("fma.rn.f32x2 %0, %1, %2, %0;" : "+l"(d) : "l"(a), "l"(b));
}
__device__ __forceinline__ unsigned long long dupf(float x){
    unsigned long long r;
    asm("mov.b64 %0, {%1, %1};" : "=l"(r) : "f"(x));
    return r;
}
__device__ __forceinline__ float2 u2f(unsigned long long x){
    float2 r;
    asm("mov.b64 {%0, %1}, %2;" : "=f"(r.x), "=f"(r.y) : "l"(x));
    return r;
}

// ---------------- scratch (static device globals; no allocation) -------------
__device__ float d_A[3*MATSZ];        // dense adjacency counts, zero padded
__device__ float d_invcnt[3*RPAD];
__device__ float d_h1[NN*DD];
__device__ float d_y1[3*NN*DD];
__device__ float d_h2[3*NN*DD];
__device__ float d_y2[3*NN*DD];
__device__ float d_cu[NITEM*DD];
__device__ float d_ci[NUSER*DD];
__device__ float d_invcol[4*DD];
__device__ float d_es[BB*DD];
__device__ float d_hb[BB*DD];
__device__ float d_mu[DD];
__device__ float d_istd[DD];

__device__ __forceinline__ float* buf(int id){
    switch(id){
        case 0: return d_h1;
        case 1: return d_y1;
        case 2: return d_h2;
        case 3: return d_y2;
        case 4: return d_es;
    }
    return d_hb;
}

// ---------------- zero adjacency ---------------------------------------------
__global__ void k_zeroA(){
    int i = blockIdx.x*blockDim.x + threadIdx.x;
    int n = 3*MATSZ/4;
    if (i < n) reinterpret_cast<float4*>(d_A)[i] = make_float4(0.f,0.f,0.f,0.f);
}

// ---------------- build adjacency counts (3 graphs, one launch) --------------
__global__ void k_build3(const int* __restrict__ e0, int E0,
                         const int* __restrict__ e1, int E1,
                         const int* __restrict__ e2, int E2){
    int g = blockIdx.y;
    const int* e = (g == 0) ? e0 : (g == 1) ? e1 : e2;
    int E       = (g == 0) ? E0 : (g == 1) ? E1 : E2;
    int i = blockIdx.x*blockDim.x + threadIdx.x;
    if (i < E){
        int s = e[i];
        int d = e[E + i];
        atomicAdd(&d_A[(size_t)g*MATSZ + (size_t)d*KPAD + s], 1.0f);
    }
}

// ---------------- per-row 1/max(cnt,1) ---------------------------------------
__global__ void k_cnt(){
    int g    = blockIdx.y;
    int w    = threadIdx.x >> 5;
    int lane = threadIdx.x & 31;
    int row  = blockIdx.x*8 + w;
    if (row >= RPAD) return;
    const float* Ar = d_A + (size_t)g*MATSZ + (size_t)row*KPAD;
    float s = 0.f;
    #pragma unroll 8
    for (int k = lane; k < KPAD; k += 32) s += Ar[k];
    #pragma unroll
    for (int off = 16; off; off >>= 1) s += __shfl_xor_sync(0xffffffffu, s, off);
    if (!lane) d_invcnt[g*RPAD + row] = 1.f / fmaxf(s, 1.f);
}

// ---------------- out = x @ W^T + b  (D=64) ----------------------------------
__global__ void k_lin(const float* __restrict__ xext, int xid,
                      const float* __restrict__ W, const float* __restrict__ bias,
                      int outid, int nrows){
    const float* x = xext ? xext : buf(xid);
    float* o = buf(outid);
    __shared__ float Ws[64*65];
    int tx = threadIdx.x, ty = threadIdx.y;
    int tid = ty*64 + tx;
    for (int i = tid; i < 4096; i += 256){
        int r = i >> 6, c = i & 63;
        Ws[r*65 + c] = W[i];
    }
    __syncthreads();
    int n = blockIdx.x*4 + ty;
    if (n >= nrows) return;
    float acc = bias[tx];
    const float* xr = x + (size_t)n*64;
    #pragma unroll
    for (int k = 0; k < 64; k++) acc = fmaf(xr[k], Ws[tx*65 + k], acc);
    o[(size_t)n*64 + tx] = acc;
}

// ---------------- y = tanh(invcnt * (A @ h)), smem-tiled + FFMA2 -------------
// block (16,8): 32 rows x 64 cols per block; A tile staged DUPLICATED in smem
__global__ __launch_bounds__(128) void k_agg(int hid, int gstride, int outid){
    int g = blockIdx.y;
    const float* A = d_A + (size_t)g*MATSZ;
    const float* h = buf(hid) + (size_t)g*gstride;
    float*       o = buf(outid) + (size_t)g*NN*DD;
    int tx = threadIdx.x;   // 0..15 : d float4 group
    int ty = threadIdx.y;   // 0..7  : 4-row group
    int tid = ty*16 + tx;
    __shared__ float As2[32*132];   // A tile, each value duplicated: As2[r][2k]=As2[r][2k+1]
    __shared__ float hs[64*64];     // h tile [j][d]

    unsigned long long acc[4][2] = {{0,0},{0,0},{0,0},{0,0}};
    int n0 = blockIdx.x*32;

    for (int kt = 0; kt < 19; kt++){
        int k0 = kt*64;
        // stage A tile 32x64, duplicated pairs (coalesced float4 global reads)
        #pragma unroll
        for (int i = tid; i < 512; i += 128){
            int r = i >> 4, c4 = i & 15;
            float4 v = *reinterpret_cast<const float4*>(
                          &A[(size_t)(n0 + r)*KPAD + k0 + c4*4]);
            *reinterpret_cast<float4*>(&As2[r*132 + c4*8    ]) =
                make_float4(v.x, v.x, v.y, v.y);
            *reinterpret_cast<float4*>(&As2[r*132 + c4*8 + 4]) =
                make_float4(v.z, v.z, v.w, v.w);
        }
        // stage h tile 64x64
        #pragma unroll
        for (int i = tid; i < 1024; i += 128){
            int jr = i >> 4, c4 = i & 15;
            int gk = k0 + jr;
            float4 v = (gk < NN) ? reinterpret_cast<const float4*>(h)[gk*16 + c4]
                                 : make_float4(0,0,0,0);
            *reinterpret_cast<float4*>(&hs[jr*64 + c4*4]) = v;
        }
        __syncthreads();
        const float* Ar = &As2[ty*4*132];
        #pragma unroll 8
        for (int j = 0; j < 64; j++){
            ulonglong2 hv = *reinterpret_cast<const ulonglong2*>(&hs[j*64 + tx*4]);
            unsigned long long a0 = *reinterpret_cast<const unsigned long long*>(&Ar[          2*j]);
            unsigned long long a1 = *reinterpret_cast<const unsigned long long*>(&Ar[  132 +   2*j]);
            unsigned long long a2 = *reinterpret_cast<const unsigned long long*>(&Ar[2*132 +   2*j]);
            unsigned long long a3 = *reinterpret_cast<const unsigned long long*>(&Ar[3*132 +   2*j]);
            fma2(acc[0][0], a0, hv.x); fma2(acc[0][1], a0, hv.y);
            fma2(acc[1][0], a1, hv.x); fma2(acc[1][1], a1, hv.y);
            fma2(acc[2][0], a2, hv.x); fma2(acc[2][1], a2, hv.y);
            fma2(acc[3][0], a3, hv.x); fma2(acc[3][1], a3, hv.y);
        }
        __syncthreads();
    }
    #pragma unroll
    for (int r = 0; r < 4; r++){
        int n = n0 + ty*4 + r;
        if (n < NN){
            float ic = d_invcnt[g*RPAD + n];
            float2 p0 = u2f(acc[r][0]);
            float2 p1 = u2f(acc[r][1]);
            float4 v;
            v.x = tanhf(ic*p0.x); v.y = tanhf(ic*p0.y);
            v.z = tanhf(ic*p1.x); v.w = tanhf(ic*p1.y);
            reinterpret_cast<float4*>(o)[n*16 + tx] = v;
        }
    }
}

// ---------------- column L2 inv-norms over user rows (4 matrices) ------------
__global__ void k_colnorm(const float* __restrict__ emb){
    int dcol = blockIdx.x, m = blockIdx.y;
    const float* x = (m == 0) ? emb
                   : (m == 1) ? d_y2 + NN*DD      // SH_g3  (sub_g1)
                   : (m == 2) ? d_y2              // x_SH6  (total_g)
                   :            d_y2 + 2*NN*DD;   // SH_g33 (sub_g2)
    float s = 0.f;
    for (int r = threadIdx.x; r < NUSER; r += 256){
        float v = x[(size_t)r*64 + dcol];
        s = fmaf(v, v, s);
    }
    __shared__ float sh[256];
    sh[threadIdx.x] = s; __syncthreads();
    for (int o = 128; o; o >>= 1){
        if (threadIdx.x < o) sh[threadIdx.x] += sh[threadIdx.x + o];
        __syncthreads();
    }
    if (!threadIdx.x) d_invcol[m*64 + dcol] = rsqrtf(sh[0]);
}

// ---------------- c_u : fused row-normalized item views ----------------------
__global__ void k_cu(const float* __restrict__ emb){
    int w    = threadIdx.x >> 5;
    int lane = threadIdx.x & 31;
    int r = blockIdx.x*8 + w;
    if (r >= NITEM) return;
    size_t row = (size_t)(NUSER + r)*64;
    const float* mats[4] = { emb, d_y2 + NN*DD, d_y2, d_y2 + 2*NN*DD };
    float o0 = 0.f, o1 = 0.f;
    #pragma unroll
    for (int m = 0; m < 4; m++){
        float a = mats[m][row + lane];
        float b = mats[m][row + lane + 32];
        float ss = a*a + b*b;
        #pragma unroll
        for (int off = 16; off; off >>= 1) ss += __shfl_xor_sync(0xffffffffu, ss, off);
        float inv = rsqrtf(ss);
        o0 = fmaf(a, inv, o0);
        o1 = fmaf(b, inv, o1);
    }
    d_cu[r*64 + lane]      = 0.25f*o0;
    d_cu[r*64 + lane + 32] = 0.25f*o1;
}

// ---------------- c_i : fused column-normalized user views -------------------
__global__ void k_ci(const float* __restrict__ emb){
    int i = blockIdx.x*256 + threadIdx.x;
    if (i >= NUSER*64) return;
    int dcol = i & 63;
    float v = emb[i]             * d_invcol[       dcol]
            + d_y2[NN*DD + i]    * d_invcol[ 64  + dcol]
            + d_y2[i]            * d_invcol[128  + dcol]
            + d_y2[2*NN*DD + i]  * d_invcol[192  + dcol];
    d_ci[i] = 0.25f*v;
}

// ---------------- e_synd = (presc @ c_u) / rowsum(presc) ---------------------
__global__ void k_esynd(const float* __restrict__ presc){
    int tx = threadIdx.x, ty = threadIdx.y;
    int tid = ty*16 + tx;
    int n = blockIdx.x*16 + ty;
    __shared__ float4 cus[64*16];
    float4 acc = make_float4(0,0,0,0);
    float rs = 0.f;
    for (int k0 = 0; k0 < NITEM; k0 += 64){
        for (int i = tid; i < 1024; i += 256){
            int r = i >> 4, c = i & 15;
            int gk = k0 + r;
            cus[i] = (gk < NITEM) ? reinterpret_cast<const float4*>(d_cu)[gk*16 + c]
                                  : make_float4(0,0,0,0);
        }
        __syncthreads();
        int jm = min(64, NITEM - k0);
        for (int j = 0; j < jm; j++){
            float a = presc[(size_t)n*NITEM + k0 + j];
            rs += a;
            float4 cv = cus[j*16 + tx];
            acc.x = fmaf(a, cv.x, acc.x); acc.y = fmaf(a, cv.y, acc.y);
            acc.z = fmaf(a, cv.z, acc.z); acc.w = fmaf(a, cv.w, acc.w);
        }
        __syncthreads();
    }
    float inv = 1.f/rs;
    float4 v = make_float4(acc.x*inv, acc.y*inv, acc.z*inv, acc.w*inv);
    reinterpret_cast<float4*>(d_es)[n*16 + tx] = v;
}

// ---------------- BN stats over batch ----------------------------------------
__global__ void k_bnstats(){
    int c = blockIdx.x;
    float s = 0.f, s2 = 0.f;
    for (int r = threadIdx.x; r < BB; r += 256){
        float v = d_hb[(size_t)r*64 + c];
        s += v; s2 = fmaf(v, v, s2);
    }
    __shared__ float sha[256], shb[256];
    sha[threadIdx.x] = s; shb[threadIdx.x] = s2; __syncthreads();
    for (int o = 128; o; o >>= 1){
        if (threadIdx.x < o){
            sha[threadIdx.x] += sha[threadIdx.x + o];
            shb[threadIdx.x] += shb[threadIdx.x + o];
        }
        __syncthreads();
    }
    if (!threadIdx.x){
        float mu  = sha[0] / (float)BB;
        float var = shb[0] / (float)BB - mu*mu;
        d_mu[c]   = mu;
        d_istd[c] = rsqrtf(var + 1e-5f);
    }
}

// ---------------- pre = relu(BN(hb)) @ c_i^T  (BN fused into tile load) ------
__global__ __launch_bounds__(256) void k_final(float* __restrict__ out,
                                               const float* __restrict__ gamma,
                                               const float* __restrict__ beta){
    int tx = threadIdx.x, ty = threadIdx.y;
    int tid = ty*16 + tx;
    int j0 = blockIdx.x*64;
    int n0 = blockIdx.y*64;
    __shared__ float cit[64*68];   // cit[k][j], padded
    __shared__ float hsm[64*68];   // hsm[n][k], padded (BN+relu applied)
    for (int i = tid; i < 1024; i += 256){
        int r = i >> 4, c4 = i & 15;
        float4 hv = reinterpret_cast<const float4*>(d_hb)[(size_t)(n0 + r)*16 + c4];
        int c = c4*4;
        hv.x = fmaxf((hv.x - d_mu[c  ])*d_istd[c  ]*gamma[c  ] + beta[c  ], 0.f);
        hv.y = fmaxf((hv.y - d_mu[c+1])*d_istd[c+1]*gamma[c+1] + beta[c+1], 0.f);
        hv.z = fmaxf((hv.z - d_mu[c+2])*d_istd[c+2]*gamma[c+2] + beta[c+2], 0.f);
        hv.w = fmaxf((hv.w - d_mu[c+3])*d_istd[c+3]*gamma[c+3] + beta[c+3], 0.f);
        *reinterpret_cast<float4*>(&hsm[r*68 + c]) = hv;
        float4 v = (j0 + r < NUSER)
            ? reinterpret_cast<const float4*>(d_ci)[(size_t)(j0 + r)*16 + c4]
            : make_float4(0,0,0,0);
        cit[(c    )*68 + r] = v.x;
        cit[(c + 1)*68 + r] = v.y;
        cit[(c + 2)*68 + r] = v.z;
        cit[(c + 3)*68 + r] = v.w;
    }
    __syncthreads();
    unsigned long long acc[4][2] = {{0,0},{0,0},{0,0},{0,0}};
    #pragma unroll 8
    for (int k = 0; k < 64; k++){
        ulonglong2 cj = *reinterpret_cast<const ulonglong2*>(&cit[k*68 + tx*4]);
        #pragma unroll
        for (int r = 0; r < 4; r++){
            unsigned long long aa = dupf(hsm[(ty*4 + r)*68 + k]);
            fma2(acc[r][0], aa, cj.x);
            fma2(acc[r][1], aa, cj.y);
        }
    }
    #pragma unroll
    for (int r = 0; r < 4; r++){
        int n = n0 + ty*4 + r;
        int j = j0 + tx*4;
        float2 p0 = u2f(acc[r][0]);
        float2 p1 = u2f(acc[r][1]);
        float vals[4] = { p0.x, p0.y, p1.x, p1.y };
        #pragma unroll
        for (int c = 0; c < 4; c++)
            if (j + c < NUSER) out[(size_t)n*NUSER + j + c] = vals[c];
    }
}

// ---------------- launch -----------------------------------------------------
extern "C" void kernel_launch(void* const* d_in, const int* in_sizes, int n_in,
                              void* d_out, int out_size){
    const float* presc = (const float*)d_in[1];
    const float* emb   = (const float*)d_in[2];
    const float* W1    = (const float*)d_in[3];
    const float* b1    = (const float*)d_in[4];
    const float* W2    = (const float*)d_in[5];
    const float* b2    = (const float*)d_in[6];
    const float* mlpW  = (const float*)d_in[7];
    const float* mlpb  = (const float*)d_in[8];
    const float* gamma = (const float*)d_in[9];
    const float* beta  = (const float*)d_in[10];
    const int*   tg    = (const int*)d_in[11];
    const int*   sg1   = (const int*)d_in[12];
    const int*   sg2   = (const int*)d_in[13];
    int Et = in_sizes[11]/2;
    int E1 = in_sizes[12]/2;
    int E2 = in_sizes[13]/2;
    int Emax = Et > E1 ? Et : E1; if (E2 > Emax) Emax = E2;
    float* out = (float*)d_out;

    // adjacency build
    k_zeroA<<<(3*MATSZ/4 + 255)/256, 256>>>();
    k_build3<<<dim3((Emax + 255)/256, 3), 256>>>(tg, Et, sg1, E1, sg2, E2);
    k_cnt<<<dim3(RPAD/8, 3), 256>>>();

    // GCN layer 1 (shared linear transform) + layer 2
    k_lin<<<(NN + 3)/4, dim3(64,4)>>>(emb, -1, W1, b1, 0, NN);
    k_agg<<<dim3((NN + 31)/32, 3), dim3(16,8)>>>(0, 0, 1);
    k_lin<<<(3*NN + 3)/4, dim3(64,4)>>>(nullptr, 1, W2, b2, 2, 3*NN);
    k_agg<<<dim3((NN + 31)/32, 3), dim3(16,8)>>>(2, NN*DD, 3);

    // contrastive-view fusion
    k_colnorm<<<dim3(64,4), 256>>>(emb);
    k_cu<<<(NITEM + 7)/8, 256>>>(emb);
    k_ci<<<(NUSER*64 + 255)/256, 256>>>(emb);

    // prescription pooling -> MLP -> BN(+relu fused) -> scores
    k_esynd<<<BB/16, dim3(16,16)>>>(presc);
    k_lin<<<BB/4, dim3(64,4)>>>(nullptr, 4, mlpW, mlpb, 5, BB);
    k_bnstats<<<64, 256>>>();
    k_final<<<dim3((NUSER + 63)/64, BB/64), dim3(16,16)>>>(out, gamma, beta);
}

// round 4
// speedup vs baseline: 1.3680x; 1.2546x over previous
#include <cuda_runtime.h>
#include <math.h>

#define NN     1195
#define NUSER  805
#define NITEM  390
#define BB     2048
#define KPAD   1216           // A col stride (19 tiles of 64)
#define RA     1280           // A row alloc (10 blocks of 128)
#define MATSZ  (RA*KPAD)
#define CHS    (3*RA*64)      // pacc chunk stride (floats)

// ---------------- packed f32x2 helpers (Blackwell FFMA2) ---------------------
__device__ __forceinline__ void fma2(unsigned long long& d,
                                     unsigned long long a, unsigned long long b){
    asm("fma.rn.f32x2 %0, %1, %2, %0;" : "+l"(d) : "l"(a), "l"(b));
}
__device__ __forceinline__ unsigned long long dupf(float x){
    unsigned long long r;
    asm("mov.b64 %0, {%1, %1};" : "=l"(r) : "f"(x));
    return r;
}
__device__ __forceinline__ float2 u2f(unsigned long long x){
    float2 r;
    asm("mov.b64 {%0, %1}, %2;" : "=f"(r.x), "=f"(r.y) : "l"(x));
    return r;
}

// ---------------- scratch ----------------------------------------------------
__device__ float d_A[3*MATSZ];
__device__ float d_invcnt[3*RA];
__device__ float d_h1[NN*64];
__device__ float d_h2[3*NN*64];
__device__ float d_pacc[4*CHS];       // [chunk][g][row][64], plain stores
__device__ float d_y2[3*NN*64];
__device__ float d_cu[NITEM*64];
__device__ float d_ci[NUSER*64];
__device__ float d_invcol[4*64];
__device__ float d_hb[BB*64];
__device__ float d_mu[64];
__device__ float d_istd[64];

// ---------------- zero adjacency ---------------------------------------------
__global__ void k_zeroA(){
    int i = blockIdx.x*blockDim.x + threadIdx.x;
    int n = 3*MATSZ/4;
    if (i < n) reinterpret_cast<float4*>(d_A)[i] = make_float4(0.f,0.f,0.f,0.f);
}

// ---------------- build adjacency counts (3 graphs, one launch) --------------
__global__ void k_build3(const int* __restrict__ e0, int E0,
                         const int* __restrict__ e1, int E1,
                         const int* __restrict__ e2, int E2){
    int g = blockIdx.y;
    const int* e = (g == 0) ? e0 : (g == 1) ? e1 : e2;
    int E       = (g == 0) ? E0 : (g == 1) ? E1 : E2;
    int i = blockIdx.x*blockDim.x + threadIdx.x;
    if (i < E){
        int s = e[i];
        int d = e[E + i];
        atomicAdd(&d_A[(size_t)g*MATSZ + (size_t)d*KPAD + s], 1.0f);
    }
}

// ---------------- invcnt = 1/max(rowsum,1), warp per row, float4 -------------
__global__ void k_cnt(){
    int g    = blockIdx.y;
    int w    = threadIdx.x >> 5;
    int lane = threadIdx.x & 31;
    int row  = blockIdx.x*8 + w;
    const float4* Ar = reinterpret_cast<const float4*>(
                          d_A + (size_t)g*MATSZ + (size_t)row*KPAD);
    float s = 0.f;
    for (int k = lane; k < KPAD/4; k += 32){
        float4 v = Ar[k];
        s += v.x + v.y + v.z + v.w;
    }
    #pragma unroll
    for (int off = 16; off; off >>= 1) s += __shfl_xor_sync(0xffffffffu, s, off);
    if (!lane) d_invcnt[g*RA + row] = 1.f / fmaxf(s, 1.f);
}

// ---------------- h1 = emb @ W1^T + b1 (64 rows per block) -------------------
__global__ __launch_bounds__(256) void k_lin1(const float* __restrict__ x,
                                              const float* __restrict__ W,
                                              const float* __restrict__ b){
    __shared__ float Ws[64*65];
    __shared__ float xs[64*68];
    int tx = threadIdx.x, ty = threadIdx.y;
    int tid = ty*64 + tx;
    int n0 = blockIdx.x*64;
    for (int i = tid; i < 4096; i += 256) Ws[(i>>6)*65 + (i&63)] = W[i];
    for (int i = tid; i < 1024; i += 256){
        int r = i>>4, c4 = i&15;
        float4 v = (n0 + r < NN) ? reinterpret_cast<const float4*>(x)[(n0+r)*16 + c4]
                                 : make_float4(0,0,0,0);
        *reinterpret_cast<float4*>(&xs[r*68 + c4*4]) = v;
    }
    __syncthreads();
    float bb = b[tx];
    #pragma unroll
    for (int i = 0; i < 16; i++){
        int rl = ty*16 + i;
        int n = n0 + rl;
        if (n >= NN) break;
        float acc = bb;
        #pragma unroll
        for (int k = 0; k < 64; k++) acc = fmaf(xs[rl*68 + k], Ws[tx*65 + k], acc);
        d_h1[n*64 + tx] = acc;
    }
}

// ---------------- pacc[chunk] = A_chunk @ h  (128x64 tile, 8x8/thread) -------
__global__ __launch_bounds__(128) void k_agg(int layer){
    const int g  = blockIdx.y;
    const int cz = blockIdx.z;
    const float* A = d_A + (size_t)g*MATSZ;
    const float* h = (layer == 1) ? d_h1 : d_h2 + g*NN*64;
    __shared__ float As[128*64];   // xor-swizzled
    __shared__ float hs[64*64];
    int tx = threadIdx.x;          // 0..7  : 8-col group
    int ty = threadIdx.y;          // 0..15 : 8-row group
    int tid = ty*8 + tx;
    int n0 = blockIdx.x*128;
    int s8 = (ty & 3) << 3;        // row-group read swizzle (row>>3 & 3)<<3
    unsigned long long acc[8][4];
    #pragma unroll
    for (int r = 0; r < 8; r++){
        acc[r][0] = 0ull; acc[r][1] = 0ull; acc[r][2] = 0ull; acc[r][3] = 0ull;
    }
    int t0 = cz*5, t1 = (cz == 3) ? 19 : cz*5 + 5;
    for (int t = t0; t < t1; t++){
        int k0 = t*64;
        #pragma unroll
        for (int i = tid; i < 2048; i += 128){
            int r = i>>4, c4 = i&15;
            float4 v = *reinterpret_cast<const float4*>(
                          &A[(size_t)(n0 + r)*KPAD + k0 + c4*4]);
            int sw = ((r>>3) & 3) << 3;
            *reinterpret_cast<float4*>(&As[r*64 + ((c4*4) ^ sw)]) = v;
        }
        #pragma unroll
        for (int i = tid; i < 1024; i += 128){
            int jr = i>>4, c4 = i&15;
            int gk = k0 + jr;
            float4 v = (gk < NN) ? reinterpret_cast<const float4*>(h)[gk*16 + c4]
                                 : make_float4(0,0,0,0);
            *reinterpret_cast<float4*>(&hs[jr*64 + c4*4]) = v;
        }
        __syncthreads();
        #pragma unroll 2
        for (int j = 0; j < 64; j++){
            ulonglong2 ha = *reinterpret_cast<const ulonglong2*>(&hs[j*64 + tx*8]);
            ulonglong2 hb2 = *reinterpret_cast<const ulonglong2*>(&hs[j*64 + tx*8 + 4]);
            int jc = j ^ s8;
            #pragma unroll
            for (int r = 0; r < 8; r++){
                unsigned long long a = dupf(As[(ty*8 + r)*64 + jc]);
                fma2(acc[r][0], a, ha.x);  fma2(acc[r][1], a, ha.y);
                fma2(acc[r][2], a, hb2.x); fma2(acc[r][3], a, hb2.y);
            }
        }
        __syncthreads();
    }
    float* p = d_pacc + (size_t)cz*CHS + ((size_t)g*RA)*64;
    #pragma unroll
    for (int r = 0; r < 8; r++){
        size_t row = n0 + ty*8 + r;
        ulonglong2 v0; v0.x = acc[r][0]; v0.y = acc[r][1];
        ulonglong2 v1; v1.x = acc[r][2]; v1.y = acc[r][3];
        *reinterpret_cast<ulonglong2*>(&p[row*64 + tx*8    ]) = v0;
        *reinterpret_cast<ulonglong2*>(&p[row*64 + tx*8 + 4]) = v1;
    }
}

// ---------------- fin1: y1=tanh(ic*sum(pacc)); h2 = y1 @ W2^T + b2 -----------
__global__ __launch_bounds__(256) void k_fin1(const float* __restrict__ W2,
                                              const float* __restrict__ b2){
    int g = blockIdx.y;
    int n0 = blockIdx.x*64;
    __shared__ float Ws[64*65];
    __shared__ float ys[64*68];
    int tid = threadIdx.x;
    for (int i = tid; i < 4096; i += 256) Ws[(i>>6)*65 + (i&63)] = W2[i];
    for (int i = tid; i < 1024; i += 256){
        int r = i>>4, c4 = i&15;
        size_t row = n0 + r;
        size_t off = ((size_t)g*RA + row)*16 + c4;    // float4 units
        float4 v0 = reinterpret_cast<const float4*>(d_pacc)[off];
        float4 v1 = reinterpret_cast<const float4*>(d_pacc)[off + CHS/4];
        float4 v2 = reinterpret_cast<const float4*>(d_pacc)[off + 2*(CHS/4)];
        float4 v3 = reinterpret_cast<const float4*>(d_pacc)[off + 3*(CHS/4)];
        float ic = d_invcnt[g*RA + row];
        float4 o;
        o.x = tanhf(ic*(v0.x + v1.x + v2.x + v3.x));
        o.y = tanhf(ic*(v0.y + v1.y + v2.y + v3.y));
        o.z = tanhf(ic*(v0.z + v1.z + v2.z + v3.z));
        o.w = tanhf(ic*(v0.w + v1.w + v2.w + v3.w));
        *reinterpret_cast<float4*>(&ys[r*68 + c4*4]) = o;
    }
    __syncthreads();
    int tx = tid & 63, ty = tid >> 6;
    float bb = b2[tx];
    #pragma unroll
    for (int i = 0; i < 16; i++){
        int rl = ty*16 + i;
        int n = n0 + rl;
        if (n >= NN) break;
        float acc = bb;
        #pragma unroll
        for (int k = 0; k < 64; k++) acc = fmaf(ys[rl*68 + k], Ws[tx*65 + k], acc);
        d_h2[((size_t)g*NN + n)*64 + tx] = acc;
    }
}

// ---------------- fin2: y2 = tanh(ic * sum(pacc)) ----------------------------
__global__ void k_fin2(){
    int i = blockIdx.x*256 + threadIdx.x;      // float4 index
    if (i >= 3*NN*16) return;
    int gm = i / (NN*16);
    int rem = i - gm*NN*16;
    int row = rem >> 4, c4 = rem & 15;
    size_t off = ((size_t)gm*RA + row)*16 + c4;
    float4 v0 = reinterpret_cast<const float4*>(d_pacc)[off];
    float4 v1 = reinterpret_cast<const float4*>(d_pacc)[off + CHS/4];
    float4 v2 = reinterpret_cast<const float4*>(d_pacc)[off + 2*(CHS/4)];
    float4 v3 = reinterpret_cast<const float4*>(d_pacc)[off + 3*(CHS/4)];
    float ic = d_invcnt[gm*RA + row];
    float4 o;
    o.x = tanhf(ic*(v0.x + v1.x + v2.x + v3.x));
    o.y = tanhf(ic*(v0.y + v1.y + v2.y + v3.y));
    o.z = tanhf(ic*(v0.z + v1.z + v2.z + v3.z));
    o.w = tanhf(ic*(v0.w + v1.w + v2.w + v3.w));
    reinterpret_cast<float4*>(d_y2)[(size_t)(gm*NN + row)*16 + c4] = o;
}

// ---------------- colnorm (blocks 0..255) + cu (blocks 256..) ----------------
__global__ void k_cnormcu(const float* __restrict__ emb){
    int b = blockIdx.x;
    if (b < 256){
        int dcol = b & 63, m = b >> 6;
        const float* x = (m == 0) ? emb
                       : (m == 1) ? d_y2 + NN*64      // SH_g3  (sub_g1)
                       : (m == 2) ? d_y2              // x_SH6  (total_g)
                       :            d_y2 + 2*NN*64;   // SH_g33 (sub_g2)
        float s = 0.f;
        for (int r = threadIdx.x; r < NUSER; r += 256){
            float v = x[(size_t)r*64 + dcol];
            s = fmaf(v, v, s);
        }
        __shared__ float sh[256];
        sh[threadIdx.x] = s; __syncthreads();
        for (int o = 128; o; o >>= 1){
            if (threadIdx.x < o) sh[threadIdx.x] += sh[threadIdx.x + o];
            __syncthreads();
        }
        if (!threadIdx.x) d_invcol[m*64 + dcol] = rsqrtf(sh[0]);
    } else {
        int w    = threadIdx.x >> 5;
        int lane = threadIdx.x & 31;
        int r = (b - 256)*8 + w;
        if (r >= NITEM) return;
        size_t row = (size_t)(NUSER + r)*64;
        const float* mats[4] = { emb, d_y2 + NN*64, d_y2, d_y2 + 2*NN*64 };
        float o0 = 0.f, o1 = 0.f;
        #pragma unroll
        for (int m = 0; m < 4; m++){
            float a = mats[m][row + lane];
            float c = mats[m][row + lane + 32];
            float ss = a*a + c*c;
            #pragma unroll
            for (int off = 16; off; off >>= 1) ss += __shfl_xor_sync(0xffffffffu, ss, off);
            float inv = rsqrtf(ss);
            o0 = fmaf(a, inv, o0);
            o1 = fmaf(c, inv, o1);
        }
        d_cu[r*64 + lane]      = 0.25f*o0;
        d_cu[r*64 + lane + 32] = 0.25f*o1;
    }
}

// ---------------- c_i : fused column-normalized user views -------------------
__global__ void k_ci(const float* __restrict__ emb){
    int i = blockIdx.x*256 + threadIdx.x;
    if (i >= NUSER*64) return;
    int dcol = i & 63;
    float v = emb[i]             * d_invcol[       dcol]
            + d_y2[NN*64 + i]    * d_invcol[ 64  + dcol]
            + d_y2[i]            * d_invcol[128  + dcol]
            + d_y2[2*NN*64 + i]  * d_invcol[192  + dcol];
    d_ci[i] = 0.25f*v;
}

// ---------------- hb = ((presc @ c_u)/rowsum) @ mlpW^T + mlpb ----------------
__global__ __launch_bounds__(256) void k_esmlp(const float* __restrict__ presc,
                                               const float* __restrict__ W,
                                               const float* __restrict__ b){
    __shared__ float4 cus[64*16];
    __shared__ float prs[16*68];
    __shared__ float Ws[64*65];
    __shared__ float ess[16*68];
    int tx = threadIdx.x, ty = threadIdx.y;
    int tid = ty*16 + tx;
    int n0 = blockIdx.x*16;
    for (int i = tid; i < 4096; i += 256) Ws[(i>>6)*65 + (i&63)] = W[i];
    float4 acc = make_float4(0,0,0,0);
    float rs = 0.f;
    for (int k0 = 0; k0 < NITEM; k0 += 64){
        for (int i = tid; i < 1024; i += 256){
            int r = i>>4, c = i&15;
            int gk = k0 + r;
            cus[i] = (gk < NITEM) ? reinterpret_cast<const float4*>(d_cu)[gk*16 + c]
                                  : make_float4(0,0,0,0);
        }
        for (int i = tid; i < 1024; i += 256){
            int r = i>>6, c = i&63;
            int gk = k0 + c;
            prs[r*68 + c] = (gk < NITEM) ? presc[(size_t)(n0 + r)*NITEM + gk] : 0.f;
        }
        __syncthreads();
        int jm = min(64, NITEM - k0);
        for (int j = 0; j < jm; j++){
            float a = prs[ty*68 + j];
            rs += a;
            float4 cv = cus[j*16 + tx];
            acc.x = fmaf(a, cv.x, acc.x); acc.y = fmaf(a, cv.y, acc.y);
            acc.z = fmaf(a, cv.z, acc.z); acc.w = fmaf(a, cv.w, acc.w);
        }
        __syncthreads();
    }
    float inv = 1.f/rs;
    float4 ev = make_float4(acc.x*inv, acc.y*inv, acc.z*inv, acc.w*inv);
    *reinterpret_cast<float4*>(&ess[ty*68 + tx*4]) = ev;
    __syncthreads();
    float4 o;
    float* op = &o.x;
    #pragma unroll
    for (int c = 0; c < 4; c++){
        int cc = tx*4 + c;
        float s = b[cc];
        #pragma unroll
        for (int k = 0; k < 64; k++) s = fmaf(ess[ty*68 + k], Ws[cc*65 + k], s);
        op[c] = s;
    }
    reinterpret_cast<float4*>(d_hb)[(size_t)(n0 + ty)*16 + tx] = o;
}

// ---------------- BN stats over batch ----------------------------------------
__global__ void k_bnstats(){
    int c = blockIdx.x;
    float s = 0.f, s2 = 0.f;
    for (int r = threadIdx.x; r < BB; r += 256){
        float v = d_hb[(size_t)r*64 + c];
        s += v; s2 = fmaf(v, v, s2);
    }
    __shared__ float sha[256], shb[256];
    sha[threadIdx.x] = s; shb[threadIdx.x] = s2; __syncthreads();
    for (int o = 128; o; o >>= 1){
        if (threadIdx.x < o){
            sha[threadIdx.x] += sha[threadIdx.x + o];
            shb[threadIdx.x] += shb[threadIdx.x + o];
        }
        __syncthreads();
    }
    if (!threadIdx.x){
        float mu  = sha[0] / (float)BB;
        float var = shb[0] / (float)BB - mu*mu;
        d_mu[c]   = mu;
        d_istd[c] = rsqrtf(var + 1e-5f);
    }
}

// ---------------- pre = relu(BN(hb)) @ c_i^T ---------------------------------
__global__ __launch_bounds__(256) void k_final(float* __restrict__ out,
                                               const float* __restrict__ gamma,
                                               const float* __restrict__ beta){
    int tx = threadIdx.x, ty = threadIdx.y;
    int tid = ty*16 + tx;
    int j0 = blockIdx.x*64;
    int n0 = blockIdx.y*64;
    __shared__ float cit[64*68];
    __shared__ float hsm[64*68];
    for (int i = tid; i < 1024; i += 256){
        int r = i >> 4, c4 = i & 15;
        float4 hv = reinterpret_cast<const float4*>(d_hb)[(size_t)(n0 + r)*16 + c4];
        int c = c4*4;
        hv.x = fmaxf((hv.x - d_mu[c  ])*d_istd[c  ]*gamma[c  ] + beta[c  ], 0.f);
        hv.y = fmaxf((hv.y - d_mu[c+1])*d_istd[c+1]*gamma[c+1] + beta[c+1], 0.f);
        hv.z = fmaxf((hv.z - d_mu[c+2])*d_istd[c+2]*gamma[c+2] + beta[c+2], 0.f);
        hv.w = fmaxf((hv.w - d_mu[c+3])*d_istd[c+3]*gamma[c+3] + beta[c+3], 0.f);
        *reinterpret_cast<float4*>(&hsm[r*68 + c]) = hv;
        float4 v = (j0 + r < NUSER)
            ? reinterpret_cast<const float4*>(d_ci)[(size_t)(j0 + r)*16 + c4]
            : make_float4(0,0,0,0);
        cit[(c    )*68 + r] = v.x;
        cit[(c + 1)*68 + r] = v.y;
        cit[(c + 2)*68 + r] = v.z;
        cit[(c + 3)*68 + r] = v.w;
    }
    __syncthreads();
    unsigned long long acc[4][2] = {{0,0},{0,0},{0,0},{0,0}};
    #pragma unroll 8
    for (int k = 0; k < 64; k++){
        ulonglong2 cj = *reinterpret_cast<const ulonglong2*>(&cit[k*68 + tx*4]);
        #pragma unroll
        for (int r = 0; r < 4; r++){
            unsigned long long aa = dupf(hsm[(ty*4 + r)*68 + k]);
            fma2(acc[r][0], aa, cj.x);
            fma2(acc[r][1], aa, cj.y);
        }
    }
    #pragma unroll
    for (int r = 0; r < 4; r++){
        int n = n0 + ty*4 + r;
        int j = j0 + tx*4;
        float2 p0 = u2f(acc[r][0]);
        float2 p1 = u2f(acc[r][1]);
        float vals[4] = { p0.x, p0.y, p1.x, p1.y };
        #pragma unroll
        for (int c = 0; c < 4; c++)
            if (j + c < NUSER) out[(size_t)n*NUSER + j + c] = vals[c];
    }
}

// ---------------- launch -----------------------------------------------------
extern "C" void kernel_launch(void* const* d_in, const int* in_sizes, int n_in,
                              void* d_out, int out_size){
    const float* presc = (const float*)d_in[1];
    const float* emb   = (const float*)d_in[2];
    const float* W1    = (const float*)d_in[3];
    const float* b1    = (const float*)d_in[4];
    const float* W2    = (const float*)d_in[5];
    const float* b2    = (const float*)d_in[6];
    const float* mlpW  = (const float*)d_in[7];
    const float* mlpb  = (const float*)d_in[8];
    const float* gamma = (const float*)d_in[9];
    const float* beta  = (const float*)d_in[10];
    const int*   tg    = (const int*)d_in[11];
    const int*   sg1   = (const int*)d_in[12];
    const int*   sg2   = (const int*)d_in[13];
    int Et = in_sizes[11]/2;
    int E1 = in_sizes[12]/2;
    int E2 = in_sizes[13]/2;
    int Emax = Et > E1 ? Et : E1; if (E2 > Emax) Emax = E2;
    float* out = (float*)d_out;

    // adjacency build + counts
    k_zeroA<<<(3*MATSZ/4 + 255)/256, 256>>>();
    k_build3<<<dim3((Emax + 255)/256, 3), 256>>>(tg, Et, sg1, E1, sg2, E2);
    k_cnt<<<dim3(RA/8, 3), 256>>>();

    // GCN: lin1 -> agg -> (tanh + lin2 fused) -> agg -> tanh
    k_lin1<<<(NN + 63)/64, dim3(64,4)>>>(emb, W1, b1);
    k_agg<<<dim3(RA/128, 3, 4), dim3(8,16)>>>(1);
    k_fin1<<<dim3((NN + 63)/64, 3), 256>>>(W2, b2);
    k_agg<<<dim3(RA/128, 3, 4), dim3(8,16)>>>(2);
    k_fin2<<<(3*NN*16 + 255)/256, 256>>>();

    // contrastive-view fusion
    k_cnormcu<<<256 + (NITEM + 7)/8, 256>>>(emb);
    k_ci<<<(NUSER*64 + 255)/256, 256>>>(emb);

    // pooling + MLP (fused) -> BN stats -> final GEMM (BN+relu fused)
    k_esmlp<<<BB/16, dim3(16,16)>>>(presc, mlpW, mlpb);
    k_bnstats<<<64, 256>>>();
    k_final<<<dim3((NUSER + 63)/64, BB/64), dim3(16,16)>>>(out, gamma, beta);
}